// round 15
// baseline (speedup 1.0000x reference)
#include <cuda_runtime.h>
#include <cuda_bf16.h>
#include <cstdint>

// Problem constants (fixed by the reference generator)
#define F_DIM 16
#define B_GRAPHS 8
#define NVALS 9               // base + 8 segment dots
#define ACC_BLOCKS 592        // 148 SMs x 4 blocks -> single persistent wave
#define ACC_THREADS 256
#define BATCH_IT 5            // 10 LDG.128 in flight/thread (fits 64-reg occ-4 budget)
#define PASSES 2              // batched passes per work grab
#define CHUNK (PASSES * BATCH_IT * ACC_THREADS)   // 2560 float4s per grab (80KB)

// Per-block partials, transposed: g_partials[k][block]. Fully rewritten each
// launch -> no zeroing needed.
__device__ float g_partials[NVALS][ACC_BLOCKS];
// Work-stealing chunk counter + completion ticket. Both start 0 at module
// load; the LAST finishing block resets both to 0 -> deterministic replays.
__device__ unsigned int g_work;
__device__ unsigned int g_ticket;

__global__ __launch_bounds__(ACC_THREADS, 4) void fused_kernel(
    const float* __restrict__ inp,
    const float* __restrict__ tgt,
    const int* __restrict__ batch,
    float* __restrict__ out,
    int n)
{
    float base = 0.0f;
    float dots[B_GRAPHS];
#pragma unroll
    for (int b = 0; b < B_GRAPHS; b++) dots[b] = 0.0f;

    const float4* __restrict__ inp4 = reinterpret_cast<const float4*>(inp);
    const float4* __restrict__ tgt4 = reinterpret_cast<const float4*>(tgt);

    const int total4  = n * 4;                       // one float4 = quarter row
    const int T       = ACC_THREADS;
    const int tid     = threadIdx.x;
    const int nchunks = (total4 + CHUNK - 1) / CHUNK;

    int   cur_bid = -1;     // running-segment accumulator (batch is sorted)
    float cur_sum = 0.0f;

    // Ping-pong broadcast slots: slot p is rewritten only two grabs later,
    // with a barrier in between -> ONE __syncthreads per grab.
    __shared__ int s_base[2];
    int pp = 0;

    // ---- dynamic chunk loop: slow blocks grab fewer chunks -> no finish spread ----
    for (;;) {
        if (tid == 0) s_base[pp] = (int)atomicAdd(&g_work, 1u);
        __syncthreads();
        int c = s_base[pp];
        pp ^= 1;
        if (c >= nchunks) break;

        const int f0 = c * CHUNK;

        if (f0 + CHUNK <= total4) {
            // full chunk: PASSES unguarded batched passes
#pragma unroll
            for (int h = 0; h < PASSES; h++) {
                const int f = f0 + h * (BATCH_IT * T) + tid;
                float4 xs[BATCH_IT], ys[BATCH_IT];
                int    bs[BATCH_IT];
#pragma unroll
                for (int j = 0; j < BATCH_IT; j++) xs[j] = __ldcs(inp4 + f + j * T);
#pragma unroll
                for (int j = 0; j < BATCH_IT; j++) ys[j] = __ldcs(tgt4 + f + j * T);
#pragma unroll
                for (int j = 0; j < BATCH_IT; j++)
                    bs[j] = __ldg(batch + ((f + j * T) >> 2)) & (B_GRAPHS - 1);

#pragma unroll
                for (int j = 0; j < BATCH_IT; j++) {
                    float4 x = xs[j], y = ys[j];
                    float sq = 0.0f;
                    sq = fmaf(x.x, x.x, sq); sq = fmaf(x.y, x.y, sq);
                    sq = fmaf(x.z, x.z, sq); sq = fmaf(x.w, x.w, sq);
                    sq = fmaf(y.x, y.x, sq); sq = fmaf(y.y, y.y, sq);
                    sq = fmaf(y.z, y.z, sq); sq = fmaf(y.w, y.w, sq);
                    base += sq;

                    float d = 0.0f;
                    d = fmaf(x.x, y.x, d); d = fmaf(x.y, y.y, d);
                    d = fmaf(x.z, y.z, d); d = fmaf(x.w, y.w, d);

                    if (bs[j] != cur_bid) {   // rare: batch is sorted
                        if (cur_bid >= 0) {
#pragma unroll
                            for (int b = 0; b < B_GRAPHS; b++)
                                if (cur_bid == b) dots[b] += cur_sum;
                        }
                        cur_bid = bs[j];
                        cur_sum = 0.0f;
                    }
                    cur_sum += d;
                }
            }
        } else {
            // tail chunk: guarded scalar path
            for (int f = f0 + tid; f < total4; f += T) {
                float4 x = __ldcs(inp4 + f);
                float4 y = __ldcs(tgt4 + f);
                int bid = __ldg(batch + (f >> 2)) & (B_GRAPHS - 1);

                float sq = 0.0f;
                sq = fmaf(x.x, x.x, sq); sq = fmaf(x.y, x.y, sq);
                sq = fmaf(x.z, x.z, sq); sq = fmaf(x.w, x.w, sq);
                sq = fmaf(y.x, y.x, sq); sq = fmaf(y.y, y.y, sq);
                sq = fmaf(y.z, y.z, sq); sq = fmaf(y.w, y.w, sq);
                base += sq;

                float d = 0.0f;
                d = fmaf(x.x, y.x, d); d = fmaf(x.y, y.y, d);
                d = fmaf(x.z, y.z, d); d = fmaf(x.w, y.w, d);

                if (bid != cur_bid) {
                    if (cur_bid >= 0) {
#pragma unroll
                        for (int b = 0; b < B_GRAPHS; b++)
                            if (cur_bid == b) dots[b] += cur_sum;
                    }
                    cur_bid = bid; cur_sum = 0.0f;
                }
                cur_sum += d;
            }
        }
    }

    // final flush
    if (cur_bid >= 0) {
#pragma unroll
        for (int b = 0; b < B_GRAPHS; b++)
            if (cur_bid == b) dots[b] += cur_sum;
    }

    // ----- block reduce of the 9 values -----
    float vals[NVALS];
    vals[0] = base;
#pragma unroll
    for (int b = 0; b < B_GRAPHS; b++) vals[b + 1] = dots[b];

#pragma unroll
    for (int k = 0; k < NVALS; k++) {
#pragma unroll
        for (int off = 16; off > 0; off >>= 1)
            vals[k] += __shfl_down_sync(0xFFFFFFFFu, vals[k], off);
    }

    __shared__ float smem[ACC_THREADS / 32][NVALS];
    __shared__ int s_is_last;
    int warp = tid >> 5;
    int lane = tid & 31;
    if (lane == 0) {
#pragma unroll
        for (int k = 0; k < NVALS; k++) smem[warp][k] = vals[k];
    }
    __syncthreads();

    if (tid == 0) {
        float o[NVALS];
#pragma unroll
        for (int k = 0; k < NVALS; k++) o[k] = smem[0][k];
#pragma unroll
        for (int w = 1; w < ACC_THREADS / 32; w++) {
#pragma unroll
            for (int k = 0; k < NVALS; k++) o[k] += smem[w][k];
        }
#pragma unroll
        for (int k = 0; k < NVALS; k++)
            g_partials[k][blockIdx.x] = o[k];

        __threadfence();
        unsigned int ticket = atomicAdd(&g_ticket, 1u);
        s_is_last = (ticket == (unsigned)(gridDim.x - 1)) ? 1 : 0;
    }
    __syncthreads();

    if (!s_is_last) return;

    // ----- last block: reduce all partials -----
    __threadfence();   // acquire side of the ticket handshake
    float fv[NVALS];
#pragma unroll
    for (int k = 0; k < NVALS; k++) fv[k] = 0.0f;

    for (int r = tid; r < ACC_BLOCKS; r += ACC_THREADS) {
#pragma unroll
        for (int k = 0; k < NVALS; k++)
            fv[k] += g_partials[k][r];
    }

#pragma unroll
    for (int k = 0; k < NVALS; k++) {
#pragma unroll
        for (int off = 16; off > 0; off >>= 1)
            fv[k] += __shfl_down_sync(0xFFFFFFFFu, fv[k], off);
    }

    __syncthreads();   // smem reuse
    if (lane == 0) {
#pragma unroll
        for (int k = 0; k < NVALS; k++) smem[warp][k] = fv[k];
    }
    __syncthreads();

    if (tid == 0) {
        float acc[NVALS];
#pragma unroll
        for (int k = 0; k < NVALS; k++) acc[k] = smem[0][k];
#pragma unroll
        for (int w = 1; w < ACC_THREADS / 32; w++) {
#pragma unroll
            for (int k = 0; k < NVALS; k++) acc[k] += smem[w][k];
        }
        // min over all 2^B sign combos == base - 2 * sum_b |dot_b|
        float s = 0.0f;
#pragma unroll
        for (int b = 0; b < B_GRAPHS; b++) s += fabsf(acc[b + 1]);
        out[0] = acc[0] - 2.0f * s;
        g_work   = 0u;   // reset for next graph replay
        g_ticket = 0u;
    }
}

extern "C" void kernel_launch(void* const* d_in, const int* in_sizes, int n_in,
                              void* d_out, int out_size)
{
    const float* inp   = (const float*)d_in[0];
    const float* tgt   = (const float*)d_in[1];
    const int*   batch = (const int*)d_in[2];
    float* out = (float*)d_out;

    int n = in_sizes[2];  // number of nodes (batch vector length)

    fused_kernel<<<ACC_BLOCKS, ACC_THREADS>>>(inp, tgt, batch, out, n);
}

// round 17
// speedup vs baseline: 1.0471x; 1.0471x over previous
#include <cuda_runtime.h>
#include <cuda_bf16.h>
#include <cstdint>

// Problem constants (fixed by the reference generator)
#define F_DIM 16
#define B_GRAPHS 8
#define NVALS 9               // base + 8 segment dots
#define ACC_BLOCKS 592        // 148 SMs x 4 blocks -> single persistent wave
#define ACC_THREADS 256
#define BATCH_IT 5            // 10 LDG.128 in flight/thread (fits 64-reg occ-4 budget)
#define CHUNK (BATCH_IT * ACC_THREADS)   // 1280 float4s per grab = 320 rows

// Per-block partials, transposed: g_partials[k][block]. Fully rewritten each
// launch -> no zeroing needed.
__device__ float g_partials[NVALS][ACC_BLOCKS];
// Work-stealing chunk counter + completion ticket. Both start 0 at module
// load; the LAST finishing block resets both to 0 -> deterministic replays.
__device__ unsigned int g_work;
__device__ unsigned int g_ticket;

__global__ __launch_bounds__(ACC_THREADS, 4) void fused_kernel(
    const float* __restrict__ inp,
    const float* __restrict__ tgt,
    const int* __restrict__ batch,
    float* __restrict__ out,
    int n)
{
    float base = 0.0f;
    float dots[B_GRAPHS];
#pragma unroll
    for (int b = 0; b < B_GRAPHS; b++) dots[b] = 0.0f;

    const float4* __restrict__ inp4 = reinterpret_cast<const float4*>(inp);
    const float4* __restrict__ tgt4 = reinterpret_cast<const float4*>(tgt);

    const int total4  = n * 4;                       // one float4 = quarter row
    const int T       = ACC_THREADS;
    const int tid     = threadIdx.x;
    const int nchunks = (total4 + CHUNK - 1) / CHUNK;

    int   cur_bid = -1;     // running-segment accumulator (batch is sorted)
    float cur_sum = 0.0f;

    __shared__ int s_base;

    // ---- dynamic chunk loop: slow blocks grab fewer chunks -> no finish spread ----
    for (;;) {
        if (tid == 0) s_base = (int)atomicAdd(&g_work, 1u);
        __syncthreads();
        int c = s_base;
        __syncthreads();              // all read before tid0 rewrites next grab
        if (c >= nchunks) break;

        const int f0 = c * CHUNK;

        if (f0 + CHUNK <= total4) {
            // Sorted batch: if first and last row of the chunk share a bid,
            // the WHOLE chunk does (~99.8% of chunks) -> stripped hot path
            // with zero per-element batch loads / compares.
            const int bidA = __ldg(batch + (f0 >> 2)) & (B_GRAPHS - 1);
            const int bidB = __ldg(batch + ((f0 + CHUNK - 1) >> 2)) & (B_GRAPHS - 1);

            if (bidA == bidB) {
                if (bidA != cur_bid) {
                    if (cur_bid >= 0) {
#pragma unroll
                        for (int b = 0; b < B_GRAPHS; b++)
                            if (cur_bid == b) dots[b] += cur_sum;
                    }
                    cur_bid = bidA;
                    cur_sum = 0.0f;
                }

                const int f = f0 + tid;
                float4 xs[BATCH_IT], ys[BATCH_IT];
#pragma unroll
                for (int j = 0; j < BATCH_IT; j++) xs[j] = __ldcs(inp4 + f + j * T);
#pragma unroll
                for (int j = 0; j < BATCH_IT; j++) ys[j] = __ldcs(tgt4 + f + j * T);

                float sq = 0.0f, cd = 0.0f;
#pragma unroll
                for (int j = 0; j < BATCH_IT; j++) {
                    float4 x = xs[j], y = ys[j];
                    sq = fmaf(x.x, x.x, sq); sq = fmaf(x.y, x.y, sq);
                    sq = fmaf(x.z, x.z, sq); sq = fmaf(x.w, x.w, sq);
                    sq = fmaf(y.x, y.x, sq); sq = fmaf(y.y, y.y, sq);
                    sq = fmaf(y.z, y.z, sq); sq = fmaf(y.w, y.w, sq);
                    cd = fmaf(x.x, y.x, cd); cd = fmaf(x.y, y.y, cd);
                    cd = fmaf(x.z, y.z, cd); cd = fmaf(x.w, y.w, cd);
                }
                base    += sq;
                cur_sum += cd;
            } else {
                // boundary chunk (rare): per-element bid path
                const int f = f0 + tid;
                float4 xs[BATCH_IT], ys[BATCH_IT];
                int    bs[BATCH_IT];
#pragma unroll
                for (int j = 0; j < BATCH_IT; j++) xs[j] = __ldcs(inp4 + f + j * T);
#pragma unroll
                for (int j = 0; j < BATCH_IT; j++) ys[j] = __ldcs(tgt4 + f + j * T);
#pragma unroll
                for (int j = 0; j < BATCH_IT; j++)
                    bs[j] = __ldg(batch + ((f + j * T) >> 2)) & (B_GRAPHS - 1);

#pragma unroll
                for (int j = 0; j < BATCH_IT; j++) {
                    float4 x = xs[j], y = ys[j];
                    float sq = 0.0f;
                    sq = fmaf(x.x, x.x, sq); sq = fmaf(x.y, x.y, sq);
                    sq = fmaf(x.z, x.z, sq); sq = fmaf(x.w, x.w, sq);
                    sq = fmaf(y.x, y.x, sq); sq = fmaf(y.y, y.y, sq);
                    sq = fmaf(y.z, y.z, sq); sq = fmaf(y.w, y.w, sq);
                    base += sq;

                    float d = 0.0f;
                    d = fmaf(x.x, y.x, d); d = fmaf(x.y, y.y, d);
                    d = fmaf(x.z, y.z, d); d = fmaf(x.w, y.w, d);

                    if (bs[j] != cur_bid) {
                        if (cur_bid >= 0) {
#pragma unroll
                            for (int b = 0; b < B_GRAPHS; b++)
                                if (cur_bid == b) dots[b] += cur_sum;
                        }
                        cur_bid = bs[j];
                        cur_sum = 0.0f;
                    }
                    cur_sum += d;
                }
            }
        } else {
            // tail chunk: guarded scalar path
            for (int f = f0 + tid; f < total4; f += T) {
                float4 x = __ldcs(inp4 + f);
                float4 y = __ldcs(tgt4 + f);
                int bid = __ldg(batch + (f >> 2)) & (B_GRAPHS - 1);

                float sq = 0.0f;
                sq = fmaf(x.x, x.x, sq); sq = fmaf(x.y, x.y, sq);
                sq = fmaf(x.z, x.z, sq); sq = fmaf(x.w, x.w, sq);
                sq = fmaf(y.x, y.x, sq); sq = fmaf(y.y, y.y, sq);
                sq = fmaf(y.z, y.z, sq); sq = fmaf(y.w, y.w, sq);
                base += sq;

                float d = 0.0f;
                d = fmaf(x.x, y.x, d); d = fmaf(x.y, y.y, d);
                d = fmaf(x.z, y.z, d); d = fmaf(x.w, y.w, d);

                if (bid != cur_bid) {
                    if (cur_bid >= 0) {
#pragma unroll
                        for (int b = 0; b < B_GRAPHS; b++)
                            if (cur_bid == b) dots[b] += cur_sum;
                    }
                    cur_bid = bid; cur_sum = 0.0f;
                }
                cur_sum += d;
            }
        }
    }

    // final flush
    if (cur_bid >= 0) {
#pragma unroll
        for (int b = 0; b < B_GRAPHS; b++)
            if (cur_bid == b) dots[b] += cur_sum;
    }

    // ----- block reduce of the 9 values -----
    float vals[NVALS];
    vals[0] = base;
#pragma unroll
    for (int b = 0; b < B_GRAPHS; b++) vals[b + 1] = dots[b];

#pragma unroll
    for (int k = 0; k < NVALS; k++) {
#pragma unroll
        for (int off = 16; off > 0; off >>= 1)
            vals[k] += __shfl_down_sync(0xFFFFFFFFu, vals[k], off);
    }

    __shared__ float smem[ACC_THREADS / 32][NVALS];
    __shared__ int s_is_last;
    int warp = tid >> 5;
    int lane = tid & 31;
    if (lane == 0) {
#pragma unroll
        for (int k = 0; k < NVALS; k++) smem[warp][k] = vals[k];
    }
    __syncthreads();

    if (tid == 0) {
        float o[NVALS];
#pragma unroll
        for (int k = 0; k < NVALS; k++) o[k] = smem[0][k];
#pragma unroll
        for (int w = 1; w < ACC_THREADS / 32; w++) {
#pragma unroll
            for (int k = 0; k < NVALS; k++) o[k] += smem[w][k];
        }
#pragma unroll
        for (int k = 0; k < NVALS; k++)
            g_partials[k][blockIdx.x] = o[k];

        __threadfence();
        unsigned int ticket = atomicAdd(&g_ticket, 1u);
        s_is_last = (ticket == (unsigned)(gridDim.x - 1)) ? 1 : 0;
    }
    __syncthreads();

    if (!s_is_last) return;

    // ----- last block: reduce all partials -----
    __threadfence();   // acquire side of the ticket handshake
    float fv[NVALS];
#pragma unroll
    for (int k = 0; k < NVALS; k++) fv[k] = 0.0f;

    for (int r = tid; r < ACC_BLOCKS; r += ACC_THREADS) {
#pragma unroll
        for (int k = 0; k < NVALS; k++)
            fv[k] += g_partials[k][r];
    }

#pragma unroll
    for (int k = 0; k < NVALS; k++) {
#pragma unroll
        for (int off = 16; off > 0; off >>= 1)
            fv[k] += __shfl_down_sync(0xFFFFFFFFu, fv[k], off);
    }

    __syncthreads();   // smem reuse
    if (lane == 0) {
#pragma unroll
        for (int k = 0; k < NVALS; k++) smem[warp][k] = fv[k];
    }
    __syncthreads();

    if (tid == 0) {
        float acc[NVALS];
#pragma unroll
        for (int k = 0; k < NVALS; k++) acc[k] = smem[0][k];
#pragma unroll
        for (int w = 1; w < ACC_THREADS / 32; w++) {
#pragma unroll
            for (int k = 0; k < NVALS; k++) acc[k] += smem[w][k];
        }
        // min over all 2^B sign combos == base - 2 * sum_b |dot_b|
        float s = 0.0f;
#pragma unroll
        for (int b = 0; b < B_GRAPHS; b++) s += fabsf(acc[b + 1]);
        out[0] = acc[0] - 2.0f * s;
        g_work   = 0u;   // reset for next graph replay
        g_ticket = 0u;
    }
}

extern "C" void kernel_launch(void* const* d_in, const int* in_sizes, int n_in,
                              void* d_out, int out_size)
{
    const float* inp   = (const float*)d_in[0];
    const float* tgt   = (const float*)d_in[1];
    const int*   batch = (const int*)d_in[2];
    float* out = (float*)d_out;

    int n = in_sizes[2];  // number of nodes (batch vector length)

    fused_kernel<<<ACC_BLOCKS, ACC_THREADS>>>(inp, tgt, batch, out, n);
}